// round 5
// baseline (speedup 1.0000x reference)
#include <cuda_runtime.h>

// Spherical harmonics embedding, L=4 -> 50 channels (re,im interleaved, m=-l..l).
// Layout: out[pt*50 + ch]. Stage per-block tile in smem, store coalesced float4.

#define TILE 128
#define NCH  50
#define SROW 51   // padded row stride (odd -> conflict-free per-thread row writes)

__global__ __launch_bounds__(TILE)
void sh_embed_kernel(const float* __restrict__ dirs,
                     float* __restrict__ out,
                     int npts)
{
    __shared__ float sm[TILE * SROW];

    const int pt = blockIdx.x * TILE + threadIdx.x;
    float* row = &sm[threadIdx.x * SROW];

    if (pt < npts) {
        const float x = dirs[pt * 3 + 0];
        const float y = dirs[pt * 3 + 1];
        const float z = dirs[pt * 3 + 2];

        const float ct = fminf(fmaxf(z, -1.0f), 1.0f);
        const float st = sqrtf(fmaxf(1.0f - ct * ct, 0.0f));

        // cos(phi), sin(phi) from x,y directly (== atan2 path)
        const float r2 = x * x + y * y;
        float cp, sp;
        if (r2 > 0.0f) {
            const float rinv = rsqrtf(r2);
            cp = x * rinv;
            sp = y * rinv;
        } else {
            cp = 1.0f; sp = 0.0f;
        }

        // cos(m*phi), sin(m*phi) via angle-addition recurrence
        const float c1 = cp,              s1 = sp;
        const float c2 = cp*c1 - sp*s1,   s2 = sp*c1 + cp*s1;
        const float c3 = cp*c2 - sp*s2,   s3 = sp*c2 + cp*s2;
        const float c4 = cp*c3 - sp*s3,   s4 = sp*c3 + cp*s3;

        // Associated Legendre (Condon-Shortley), unrolled for L=4
        const float P00 = 1.0f;
        const float P11 = -st;
        const float P22 = -3.0f * st * P11;          //  3 st^2
        const float P33 = -5.0f * st * P22;          // -15 st^3
        const float P44 = -7.0f * st * P33;          // 105 st^4
        const float P10 = ct;
        const float P21 = 3.0f * ct * P11;
        const float P32 = 5.0f * ct * P22;
        const float P43 = 7.0f * ct * P33;
        const float P20 = 0.5f * (3.0f * ct * P10 - P00);
        const float P30 = (5.0f * ct * P20 - 2.0f * P10) * (1.0f/3.0f);
        const float P40 = (7.0f * ct * P30 - 3.0f * P20) * 0.25f;
        const float P31 = 0.5f * (5.0f * ct * P21 - 3.0f * P11);
        const float P41 = (7.0f * ct * P31 - 4.0f * P21) * (1.0f/3.0f);
        const float P42 = 0.5f * (7.0f * ct * P32 - 5.0f * P22);

        // Normalization N(l,m) = sqrt((2l+1)/(4pi) * (l-m)!/(l+m)!)
        const float b00 = 0.28209479177387814f * P00;
        const float b10 = 0.48860251190291992f * P10;
        const float b11 = 0.34549414947133547f * P11;
        const float b20 = 0.63078313050504009f * P20;
        const float b21 = 0.25751613468212653f * P21;
        const float b22 = 0.12875806734106327f * P22;
        const float b30 = 0.74635266518023078f * P30;
        const float b31 = 0.21545345607610053f * P31;
        const float b32 = 0.06813236509555269f * P32;
        const float b33 = 0.02781492157551894f * P33;
        const float b40 = 0.84628437532163443f * P40;
        const float b41 = 0.18923493915151202f * P41;
        const float b42 = 0.04460310290381929f * P42;
        const float b43 = 0.01192068067522273f * P43;
        const float b44 = 0.00421459707090460f * P44;

        // l=0
        row[0]  = b00;          row[1]  = 0.0f;
        // l=1: m=-1 (s=-1), 0, +1
        row[2]  = -b11 * c1;    row[3]  =  b11 * s1;
        row[4]  =  b10;         row[5]  =  0.0f;
        row[6]  =  b11 * c1;    row[7]  =  b11 * s1;
        // l=2: m=-2 (s=+1), -1 (s=-1), 0, 1, 2
        row[8]  =  b22 * c2;    row[9]  = -b22 * s2;
        row[10] = -b21 * c1;    row[11] =  b21 * s1;
        row[12] =  b20;         row[13] =  0.0f;
        row[14] =  b21 * c1;    row[15] =  b21 * s1;
        row[16] =  b22 * c2;    row[17] =  b22 * s2;
        // l=3: m=-3 (s=-1), -2 (+1), -1 (-1), 0, 1, 2, 3
        row[18] = -b33 * c3;    row[19] =  b33 * s3;
        row[20] =  b32 * c2;    row[21] = -b32 * s2;
        row[22] = -b31 * c1;    row[23] =  b31 * s1;
        row[24] =  b30;         row[25] =  0.0f;
        row[26] =  b31 * c1;    row[27] =  b31 * s1;
        row[28] =  b32 * c2;    row[29] =  b32 * s2;
        row[30] =  b33 * c3;    row[31] =  b33 * s3;
        // l=4: m=-4 (+1), -3 (-1), -2 (+1), -1 (-1), 0, 1..4
        row[32] =  b44 * c4;    row[33] = -b44 * s4;
        row[34] = -b43 * c3;    row[35] =  b43 * s3;
        row[36] =  b42 * c2;    row[37] = -b42 * s2;
        row[38] = -b41 * c1;    row[39] =  b41 * s1;
        row[40] =  b40;         row[41] =  0.0f;
        row[42] =  b41 * c1;    row[43] =  b41 * s1;
        row[44] =  b42 * c2;    row[45] =  b42 * s2;
        row[46] =  b43 * c3;    row[47] =  b43 * s3;
        row[48] =  b44 * c4;    row[49] =  b44 * s4;
    } else {
        #pragma unroll
        for (int c = 0; c < NCH; c++) row[c] = 0.0f;
    }

    __syncthreads();

    // Coalesced float4 store of the block's contiguous output slab.
    const long long total   = (long long)npts * NCH;
    const long long baseF   = (long long)blockIdx.x * (TILE * NCH);
    float4* out4 = reinterpret_cast<float4*>(out);

    #pragma unroll
    for (int i = threadIdx.x; i < (TILE * NCH) / 4; i += TILE) {
        const int j = i * 4;                     // linear float index within tile
        if (baseF + j + 3 < total || baseF + j + 4 <= total) {
            float4 v;
            v.x = sm[((j + 0) / NCH) * SROW + (j + 0) % NCH];
            v.y = sm[((j + 1) / NCH) * SROW + (j + 1) % NCH];
            v.z = sm[((j + 2) / NCH) * SROW + (j + 2) % NCH];
            v.w = sm[((j + 3) / NCH) * SROW + (j + 3) % NCH];
            out4[baseF / 4 + i] = v;
        }
    }
}

extern "C" void kernel_launch(void* const* d_in, const int* in_sizes, int n_in,
                              void* d_out, int out_size)
{
    const float* dirs = (const float*)d_in[0];
    float* out = (float*)d_out;
    const int npts = in_sizes[0] / 3;

    const int grid = (npts + TILE - 1) / TILE;
    sh_embed_kernel<<<grid, TILE>>>(dirs, out, npts);
}

// round 7
// speedup vs baseline: 1.0970x; 1.0970x over previous
#include <cuda_runtime.h>

// Spherical harmonics embedding, L=4 -> 50 channels (re,im interleaved, m=-l..l).
// out[pt*50 + ch]. Stage per-block tile in smem (stride-52 rows, 16B aligned,
// conflict-free STS.128), drain with strength-reduced addressing + __stcs.

#define TILE 128
#define NCH  50
#define SROW 52   // 16B-aligned rows; smem idx of linear e = e + 2*(e/50)

__global__ __launch_bounds__(TILE)
void sh_embed_kernel(const float* __restrict__ dirs,
                     float* __restrict__ out,
                     int npts)
{
    __shared__ float sm[TILE * SROW];

    const int tid = threadIdx.x;
    const int pt  = blockIdx.x * TILE + tid;
    float* row = &sm[tid * SROW];

    float x = 0.0f, y = 0.0f, z = 1.0f;
    if (pt < npts) {
        x = dirs[pt * 3 + 0];
        y = dirs[pt * 3 + 1];
        z = dirs[pt * 3 + 2];
    }

    const float ct = fminf(fmaxf(z, -1.0f), 1.0f);
    const float st = sqrtf(fmaxf(1.0f - ct * ct, 0.0f));

    // cos(phi), sin(phi) from x,y directly (== atan2 path)
    const float r2 = x * x + y * y;
    float cp, sp;
    if (r2 > 0.0f) {
        const float rinv = rsqrtf(r2);
        cp = x * rinv;
        sp = y * rinv;
    } else {
        cp = 1.0f; sp = 0.0f;
    }

    // cos(m*phi), sin(m*phi) via angle-addition recurrence
    const float c1 = cp,              s1 = sp;
    const float c2 = cp*c1 - sp*s1,   s2 = sp*c1 + cp*s1;
    const float c3 = cp*c2 - sp*s2,   s3 = sp*c2 + cp*s2;
    const float c4 = cp*c3 - sp*s3,   s4 = sp*c3 + cp*s3;

    // Associated Legendre (Condon-Shortley), unrolled for L=4
    const float P00 = 1.0f;
    const float P11 = -st;
    const float P22 = -3.0f * st * P11;          //  3 st^2
    const float P33 = -5.0f * st * P22;          // -15 st^3
    const float P44 = -7.0f * st * P33;          // 105 st^4
    const float P10 = ct;
    const float P21 = 3.0f * ct * P11;
    const float P32 = 5.0f * ct * P22;
    const float P43 = 7.0f * ct * P33;
    const float P20 = 0.5f * (3.0f * ct * P10 - P00);
    const float P30 = (5.0f * ct * P20 - 2.0f * P10) * (1.0f/3.0f);
    const float P40 = (7.0f * ct * P30 - 3.0f * P20) * 0.25f;
    const float P31 = 0.5f * (5.0f * ct * P21 - 3.0f * P11);
    const float P41 = (7.0f * ct * P31 - 4.0f * P21) * (1.0f/3.0f);
    const float P42 = 0.5f * (7.0f * ct * P32 - 5.0f * P22);

    // Normalization N(l,m) = sqrt((2l+1)/(4pi) * (l-m)!/(l+m)!)
    const float b00 = 0.28209479177387814f * P00;
    const float b10 = 0.48860251190291992f * P10;
    const float b11 = 0.34549414947133547f * P11;
    const float b20 = 0.63078313050504009f * P20;
    const float b21 = 0.25751613468212653f * P21;
    const float b22 = 0.12875806734106327f * P22;
    const float b30 = 0.74635266518023078f * P30;
    const float b31 = 0.21545345607610053f * P31;
    const float b32 = 0.06813236509555269f * P32;
    const float b33 = 0.02781492157551894f * P33;
    const float b40 = 0.84628437532163443f * P40;
    const float b41 = 0.18923493915151202f * P41;
    const float b42 = 0.04460310290381929f * P42;
    const float b43 = 0.01192068067522273f * P43;
    const float b44 = 0.00421459707090460f * P44;

    // Vectorized smem writes (rows are 16B aligned with SROW=52).
    float4* row4 = reinterpret_cast<float4*>(row);
    row4[0]  = make_float4( b00,       0.0f,     -b11*c1,   b11*s1);
    row4[1]  = make_float4( b10,       0.0f,      b11*c1,   b11*s1);
    row4[2]  = make_float4( b22*c2,   -b22*s2,   -b21*c1,   b21*s1);
    row4[3]  = make_float4( b20,       0.0f,      b21*c1,   b21*s1);
    row4[4]  = make_float4( b22*c2,    b22*s2,   -b33*c3,   b33*s3);
    row4[5]  = make_float4( b32*c2,   -b32*s2,   -b31*c1,   b31*s1);
    row4[6]  = make_float4( b30,       0.0f,      b31*c1,   b31*s1);
    row4[7]  = make_float4( b32*c2,    b32*s2,    b33*c3,   b33*s3);
    row4[8]  = make_float4( b44*c4,   -b44*s4,   -b43*c3,   b43*s3);
    row4[9]  = make_float4( b42*c2,   -b42*s2,   -b41*c1,   b41*s1);
    row4[10] = make_float4( b40,       0.0f,      b41*c1,   b41*s1);
    row4[11] = make_float4( b42*c2,    b42*s2,    b43*c3,   b43*s3);
    reinterpret_cast<float2*>(row)[24] = make_float2(b44*c4, b44*s4);

    __syncthreads();

    // ---- Drain: coalesced float4 streaming stores ----
    // smem index of linear float e within tile = e + 2*(e/50).
    float4* out4 = reinterpret_cast<float4*>(out)
                 + (size_t)blockIdx.x * (TILE * NCH / 4);

    if ((blockIdx.x + 1) * TILE <= npts) {
        // Full tile (always taken for npts % TILE == 0). 1600 float4 / block.
        #pragma unroll
        for (int it = 0; it < 12; it++) {
            const int i  = tid + it * TILE;   // float4 index, < 1536
            const int j  = i * 4;
            const int r  = j / 50;            // one mul-shift div
            const int rb = (j + 2) / 50;      // handles the lone j%50==48 crossing
            float4 v;
            v.x = sm[j + 0 + 2 * r];
            v.y = sm[j + 1 + 2 * r];
            v.z = sm[j + 2 + 2 * rb];
            v.w = sm[j + 3 + 2 * rb];
            __stcs(&out4[i], v);
        }
        if (tid < 64) {                       // tail 1536..1599
            const int i  = tid + 12 * TILE;
            const int j  = i * 4;
            const int r  = j / 50;
            const int rb = (j + 2) / 50;
            float4 v;
            v.x = sm[j + 0 + 2 * r];
            v.y = sm[j + 1 + 2 * r];
            v.z = sm[j + 2 + 2 * rb];
            v.w = sm[j + 3 + 2 * rb];
            __stcs(&out4[i], v);
        }
    } else {
        // Generic guarded tail path (partial last block).
        const long long total = (long long)npts * NCH;
        const long long baseF = (long long)blockIdx.x * (TILE * NCH);
        for (int i = tid; i < TILE * NCH / 4; i += TILE) {
            const long long g = baseF + (long long)i * 4;
            if (g + 4 <= total) {
                const int j  = i * 4;
                const int r  = j / 50;
                const int rb = (j + 2) / 50;
                float4 v;
                v.x = sm[j + 0 + 2 * r];
                v.y = sm[j + 1 + 2 * r];
                v.z = sm[j + 2 + 2 * rb];
                v.w = sm[j + 3 + 2 * rb];
                __stcs(&out4[i], v);
            } else if (g < total) {
                for (int e = 0; e < 4; e++) {
                    if (g + e < total) {
                        const int jl = i * 4 + e;
                        out[g + e] = sm[jl + 2 * (jl / 50)];
                    }
                }
            }
        }
    }
}

extern "C" void kernel_launch(void* const* d_in, const int* in_sizes, int n_in,
                              void* d_out, int out_size)
{
    const float* dirs = (const float*)d_in[0];
    float* out = (float*)d_out;
    const int npts = in_sizes[0] / 3;

    const int grid = (npts + TILE - 1) / TILE;
    sh_embed_kernel<<<grid, TILE>>>(dirs, out, npts);
}